// round 1
// baseline (speedup 1.0000x reference)
#include <cuda_runtime.h>
#include <math.h>

#define Bn    2
#define Sn    2048
#define Dn    1024
#define Hn    16
#define HEADn 64
#define RANKn 204
#define BHn   (Bn*Hn)
#define Mn    (Bn*Sn)          // 4096 tokens

#define NEG_INF __int_as_float(0xff800000)

// ---------------- scratch (no allocations allowed) ----------------
__device__ float g_tmp[3][(size_t)Mn*RANKn];   // low-rank intermediates
__device__ float g_qp[(size_t)Mn*Dn];
__device__ float g_kp[(size_t)Mn*Dn];
__device__ float g_vp[(size_t)Mn*Dn];
__device__ float g_oh[(size_t)Mn*Dn];          // attention output (merged heads)
__device__ float g_rowmax[BHn*Sn];
__device__ float g_rowsum[BHn*Sn];

// ---------------- helpers ----------------
__device__ __forceinline__ unsigned fkey(float f) {
    unsigned u = __float_as_uint(f);
    return (u & 0x80000000u) ? ~u : (u | 0x80000000u);
}
__device__ __forceinline__ float funkey(unsigned k) {
    unsigned u = (k & 0x80000000u) ? (k ^ 0x80000000u) : ~k;
    return __uint_as_float(u);
}

// ---------------- generic NT GEMM: C[M,N] = A[M,K] * B[N,K]^T (+bias) ----------------
struct GemmBatch {
    const float* A[3];
    const float* Bp[3];
    const float* bias[3];
    float*       C[3];
};

__global__ __launch_bounds__(256) void gemm_nt(GemmBatch gb, int M, int N, int K, int hasBias) {
    const float* A    = gb.A[blockIdx.z];
    const float* Bp   = gb.Bp[blockIdx.z];
    const float* bias = gb.bias[blockIdx.z];
    float*       C    = gb.C[blockIdx.z];

    __shared__ float As[16][68];   // [k][m]
    __shared__ float Bs[16][68];   // [k][n]

    int t  = threadIdx.x;
    int bm = blockIdx.y * 64;
    int bn = blockIdx.x * 64;
    int tm = (t & 15) * 4;
    int tn = (t >> 4) * 4;

    float acc[4][4] = {};

    for (int k0 = 0; k0 < K; k0 += 16) {
        #pragma unroll
        for (int i = 0; i < 4; i++) {
            int idx = t + i * 256;     // 0..1023
            int row = idx >> 4;        // 0..63
            int kk  = idx & 15;
            float va = (k0 + kk < K) ? A[(size_t)(bm + row) * K + k0 + kk] : 0.f;
            As[kk][row] = va;
            float vb = ((bn + row) < N && (k0 + kk) < K) ? Bp[(size_t)(bn + row) * K + k0 + kk] : 0.f;
            Bs[kk][row] = vb;
        }
        __syncthreads();
        #pragma unroll
        for (int kk = 0; kk < 16; kk++) {
            float4 a4 = *(const float4*)&As[kk][tm];
            float4 b4 = *(const float4*)&Bs[kk][tn];
            float av[4] = {a4.x, a4.y, a4.z, a4.w};
            float bv[4] = {b4.x, b4.y, b4.z, b4.w};
            #pragma unroll
            for (int i = 0; i < 4; i++)
                #pragma unroll
                for (int j = 0; j < 4; j++)
                    acc[i][j] += av[i] * bv[j];
        }
        __syncthreads();
    }

    #pragma unroll
    for (int i = 0; i < 4; i++) {
        int row = bm + tm + i;
        #pragma unroll
        for (int j = 0; j < 4; j++) {
            int col = bn + tn + j;
            if (col < N)
                C[(size_t)row * N + col] = acc[i][j] + (hasBias ? bias[col] : 0.f);
        }
    }
}

// ---------------- Pass A: raw scores + row max ----------------
// grid: (S/64 qtiles, BH). attn gets raw scores (causal), -inf (masked in diag tile),
// 0.0 for fully-masked upper tiles (final attn value there).
__global__ __launch_bounds__(256) void attn_scores(const float* __restrict__ Qp,
                                                   const float* __restrict__ Kp,
                                                   float* __restrict__ attn,
                                                   float* __restrict__ rowmax) {
    int qt = blockIdx.x, bh = blockIdx.y;
    int b = bh / Hn, h = bh % Hn;
    int q0 = qt * 64;

    __shared__ float Qst[64][68];   // [d][q]
    __shared__ float Kst[64][68];   // [d][k]
    __shared__ unsigned rmax[64];

    int t = threadIdx.x;
    int tm = (t & 15) * 4;   // q offset
    int tn = (t >> 4) * 4;   // k offset

    // load Q tile transposed
    #pragma unroll
    for (int i = 0; i < 4; i++) {
        int idx = t + i * 256;
        int row = idx >> 4, c4 = idx & 15;
        float4 v = *(const float4*)&Qp[((size_t)(b * Sn + q0 + row)) * Dn + h * HEADn + c4 * 4];
        Qst[c4 * 4 + 0][row] = v.x;
        Qst[c4 * 4 + 1][row] = v.y;
        Qst[c4 * 4 + 2][row] = v.z;
        Qst[c4 * 4 + 3][row] = v.w;
    }
    if (t < 64) rmax[t] = 0u;   // below fkey(-inf)

    size_t abase = (size_t)bh * Sn * Sn;
    const float scale = 0.125f;   // 1/sqrt(64)

    for (int kt = 0; kt < Sn / 64; kt++) {
        int k0 = kt * 64;
        if (k0 > q0 + 63) {
            // fully masked tile: final attn = 0
            float4 z4 = {0.f, 0.f, 0.f, 0.f};
            #pragma unroll
            for (int i = 0; i < 4; i++)
                *(float4*)&attn[abase + (size_t)(q0 + tm + i) * Sn + k0 + tn] = z4;
            continue;
        }
        // load K tile transposed
        #pragma unroll
        for (int i = 0; i < 4; i++) {
            int idx = t + i * 256;
            int row = idx >> 4, c4 = idx & 15;
            float4 v = *(const float4*)&Kp[((size_t)(b * Sn + k0 + row)) * Dn + h * HEADn + c4 * 4];
            Kst[c4 * 4 + 0][row] = v.x;
            Kst[c4 * 4 + 1][row] = v.y;
            Kst[c4 * 4 + 2][row] = v.z;
            Kst[c4 * 4 + 3][row] = v.w;
        }
        __syncthreads();

        float acc[4][4] = {};
        #pragma unroll
        for (int d = 0; d < 64; d++) {
            float4 q4 = *(const float4*)&Qst[d][tm];
            float4 k4 = *(const float4*)&Kst[d][tn];
            float qv[4] = {q4.x, q4.y, q4.z, q4.w};
            float kv[4] = {k4.x, k4.y, k4.z, k4.w};
            #pragma unroll
            for (int i = 0; i < 4; i++)
                #pragma unroll
                for (int j = 0; j < 4; j++)
                    acc[i][j] += qv[i] * kv[j];
        }

        #pragma unroll
        for (int i = 0; i < 4; i++) {
            int q = q0 + tm + i;
            float m = NEG_INF;
            float w[4];
            #pragma unroll
            for (int j = 0; j < 4; j++) {
                int kcol = k0 + tn + j;
                float s = acc[i][j] * scale;
                if (kcol > q) s = NEG_INF;
                else m = fmaxf(m, s);
                w[j] = s;
            }
            float4 w4 = {w[0], w[1], w[2], w[3]};
            *(float4*)&attn[abase + (size_t)q * Sn + k0 + tn] = w4;
            if (m > NEG_INF) atomicMax(&rmax[tm + i], fkey(m));
        }
        __syncthreads();
    }
    __syncthreads();
    if (t < 64) rowmax[bh * Sn + q0 + t] = funkey(rmax[t]);
}

// ---------------- Pass B: exp (write back unnormalized), row sum, fused P*V ----------------
__global__ __launch_bounds__(256) void attn_expv(float* __restrict__ attn,
                                                 const float* __restrict__ Vp,
                                                 const float* __restrict__ rowmax,
                                                 float* __restrict__ rowsum,
                                                 float* __restrict__ Oh) {
    int qt = blockIdx.x, bh = blockIdx.y;
    int b = bh / Hn, h = bh % Hn;
    int q0 = qt * 64;

    __shared__ float Est[64][68];   // [k][q]  exp'ed tile
    __shared__ float Vs[64][68];    // [k][d]
    __shared__ float rsum[64];

    int t = threadIdx.x;
    int myrow  = t >> 2;          // exp-phase: fixed row per 4-thread group
    int kphase = (t & 3) * 16;    // 16 consecutive k per thread
    int tm = (t & 15) * 4;        // PV: q offset
    int tn = (t >> 4) * 4;        // PV: d offset

    float m = rowmax[bh * Sn + q0 + myrow];
    float l = 0.f;
    float acc[4][4] = {};

    size_t abase = (size_t)bh * Sn * Sn;
    int nkt = qt + 1;

    for (int kt = 0; kt < nkt; kt++) {
        int k0 = kt * 64;
        // exp phase: read raw scores, write e back, stage transposed in shared
        #pragma unroll
        for (int i = 0; i < 4; i++) {
            size_t off = abase + (size_t)(q0 + myrow) * Sn + k0 + kphase + i * 4;
            float4 s4 = *(const float4*)&attn[off];
            float4 e4;
            e4.x = __expf(s4.x - m);
            e4.y = __expf(s4.y - m);
            e4.z = __expf(s4.z - m);
            e4.w = __expf(s4.w - m);
            l += e4.x + e4.y + e4.z + e4.w;
            *(float4*)&attn[off] = e4;
            int kk = kphase + i * 4;
            Est[kk + 0][myrow] = e4.x;
            Est[kk + 1][myrow] = e4.y;
            Est[kk + 2][myrow] = e4.z;
            Est[kk + 3][myrow] = e4.w;
        }
        // load V tile
        #pragma unroll
        for (int i = 0; i < 4; i++) {
            int idx = t + i * 256;
            int row = idx >> 4, c4 = idx & 15;
            *(float4*)&Vs[row][c4 * 4] =
                *(const float4*)&Vp[((size_t)(b * Sn + k0 + row)) * Dn + h * HEADn + c4 * 4];
        }
        __syncthreads();

        #pragma unroll
        for (int k = 0; k < 64; k++) {
            float4 e4 = *(const float4*)&Est[k][tm];
            float4 v4 = *(const float4*)&Vs[k][tn];
            float ev[4] = {e4.x, e4.y, e4.z, e4.w};
            float vv[4] = {v4.x, v4.y, v4.z, v4.w};
            #pragma unroll
            for (int i = 0; i < 4; i++)
                #pragma unroll
                for (int j = 0; j < 4; j++)
                    acc[i][j] += ev[i] * vv[j];
        }
        __syncthreads();
    }

    // reduce l over the 4 threads owning the same row (consecutive lanes)
    l += __shfl_xor_sync(0xffffffffu, l, 1);
    l += __shfl_xor_sync(0xffffffffu, l, 2);
    if ((t & 3) == 0) rsum[myrow] = l;
    __syncthreads();
    if (t < 64) rowsum[bh * Sn + q0 + t] = rsum[t];

    // normalize and store out tile (merged-head layout [B,S,D])
    #pragma unroll
    for (int i = 0; i < 4; i++) {
        float inv = 1.f / rsum[tm + i];
        float4 o = {acc[i][0] * inv, acc[i][1] * inv, acc[i][2] * inv, acc[i][3] * inv};
        *(float4*)&Oh[((size_t)(b * Sn + q0 + tm + i)) * Dn + h * HEADn + tn] = o;
    }
}

// ---------------- Pass C: normalize attn rows ----------------
__global__ __launch_bounds__(256) void attn_norm(float* __restrict__ attn,
                                                 const float* __restrict__ rowsum) {
    int q = blockIdx.x, bh = blockIdx.y;
    float inv = 1.f / rowsum[bh * Sn + q];
    int n = ((q >> 6) + 1) * 64;   // columns touched by pass B
    size_t base = (size_t)bh * Sn * Sn + (size_t)q * Sn;
    for (int k = threadIdx.x * 4; k < n; k += blockDim.x * 4) {
        float4 v = *(float4*)&attn[base + k];
        v.x *= inv; v.y *= inv; v.z *= inv; v.w *= inv;
        *(float4*)&attn[base + k] = v;
    }
}

// ---------------- launch ----------------
extern "C" void kernel_launch(void* const* d_in, const int* in_sizes, int n_in,
                              void* d_out, int out_size) {
    (void)in_sizes; (void)n_in; (void)out_size;

    const float* q = (const float*)d_in[0];
    const float* k = (const float*)d_in[1];
    const float* v = (const float*)d_in[2];
    const float* Vq = (const float*)d_in[3];
    const float* Uq = (const float*)d_in[4];
    const float* bq = (const float*)d_in[5];
    const float* Vk = (const float*)d_in[6];
    const float* Uk = (const float*)d_in[7];
    const float* bk = (const float*)d_in[8];
    const float* Vv = (const float*)d_in[9];
    const float* Uv = (const float*)d_in[10];
    const float* bv = (const float*)d_in[11];
    const float* Vo = (const float*)d_in[12];
    const float* Uo = (const float*)d_in[13];
    const float* bo = (const float*)d_in[14];

    float* out  = (float*)d_out;
    float* attn = out + (size_t)Mn * Dn;

    void *p_tmp, *p_q, *p_k, *p_v, *p_oh, *p_rm, *p_rs;
    cudaGetSymbolAddress(&p_tmp, g_tmp);
    cudaGetSymbolAddress(&p_q, g_qp);
    cudaGetSymbolAddress(&p_k, g_kp);
    cudaGetSymbolAddress(&p_v, g_vp);
    cudaGetSymbolAddress(&p_oh, g_oh);
    cudaGetSymbolAddress(&p_rm, g_rowmax);
    cudaGetSymbolAddress(&p_rs, g_rowsum);

    float* tmp0 = (float*)p_tmp;
    float* tmp1 = tmp0 + (size_t)Mn * RANKn;
    float* tmp2 = tmp1 + (size_t)Mn * RANKn;
    float* gq = (float*)p_q;
    float* gk = (float*)p_k;
    float* gv = (float*)p_v;
    float* goh = (float*)p_oh;
    float* grm = (float*)p_rm;
    float* grs = (float*)p_rs;

    // 1) low-rank down-projection for q,k,v:  tmp = x @ V^T   [4096,204]
    GemmBatch g1;
    g1.A[0] = q;  g1.A[1] = k;  g1.A[2] = v;
    g1.Bp[0] = Vq; g1.Bp[1] = Vk; g1.Bp[2] = Vv;
    g1.bias[0] = g1.bias[1] = g1.bias[2] = nullptr;
    g1.C[0] = tmp0; g1.C[1] = tmp1; g1.C[2] = tmp2;
    gemm_nt<<<dim3((RANKn + 63) / 64, Mn / 64, 3), 256>>>(g1, Mn, RANKn, Dn, 0);

    // 2) up-projection: proj = tmp @ U^T + b   [4096,1024]
    GemmBatch g2;
    g2.A[0] = tmp0; g2.A[1] = tmp1; g2.A[2] = tmp2;
    g2.Bp[0] = Uq; g2.Bp[1] = Uk; g2.Bp[2] = Uv;
    g2.bias[0] = bq; g2.bias[1] = bk; g2.bias[2] = bv;
    g2.C[0] = gq; g2.C[1] = gk; g2.C[2] = gv;
    gemm_nt<<<dim3(Dn / 64, Mn / 64, 3), 256>>>(g2, Mn, Dn, RANKn, 1);

    // 3) attention
    attn_scores<<<dim3(Sn / 64, BHn), 256>>>(gq, gk, attn, grm);
    attn_expv  <<<dim3(Sn / 64, BHn), 256>>>(attn, gv, grm, grs, goh);
    attn_norm  <<<dim3(Sn, BHn), 256>>>(attn, grs);

    // 4) output projection
    GemmBatch g3;
    g3.A[0] = goh; g3.Bp[0] = Vo; g3.bias[0] = nullptr; g3.C[0] = tmp0;
    g3.A[1] = g3.A[2] = nullptr; g3.Bp[1] = g3.Bp[2] = nullptr;
    g3.bias[1] = g3.bias[2] = nullptr; g3.C[1] = g3.C[2] = nullptr;
    gemm_nt<<<dim3((RANKn + 63) / 64, Mn / 64, 1), 256>>>(g3, Mn, RANKn, Dn, 0);

    GemmBatch g4;
    g4.A[0] = tmp0; g4.Bp[0] = Uo; g4.bias[0] = bo; g4.C[0] = out;
    g4.A[1] = g4.A[2] = nullptr; g4.Bp[1] = g4.Bp[2] = nullptr;
    g4.bias[1] = g4.bias[2] = nullptr; g4.C[1] = g4.C[2] = nullptr;
    gemm_nt<<<dim3(Dn / 64, Mn / 64, 1), 256>>>(g4, Mn, Dn, RANKn, 1);
}

// round 2
// speedup vs baseline: 2.1725x; 2.1725x over previous
#include <cuda_runtime.h>
#include <math.h>

#define Bn    2
#define Sn    2048
#define Dn    1024
#define Hn    16
#define HEADn 64
#define RANKn 204
#define BHn   (Bn*Hn)
#define Mn    (Bn*Sn)

// ---------------- scratch ----------------
__device__ float g_tmp[3][(size_t)Mn*RANKn];
__device__ float g_qp[(size_t)Mn*Dn];
__device__ float g_kp[(size_t)Mn*Dn];
__device__ float g_vp[(size_t)Mn*Dn];
__device__ float g_oh[(size_t)Mn*Dn];
__device__ float g_rowsum[BHn*Sn];

// ---------------- helpers ----------------
__device__ __forceinline__ float tf32_rna(float a) {
    unsigned r;
    asm("cvt.rna.tf32.f32 %0, %1;" : "=r"(r) : "f"(a));
    return __uint_as_float(r);
}

__device__ __forceinline__ void mma_tf32(float4& d, const float* a, const float* b) {
    asm volatile(
        "mma.sync.aligned.m16n8k8.row.col.f32.tf32.tf32.f32 "
        "{%0,%1,%2,%3},{%4,%5,%6,%7},{%8,%9},{%0,%1,%2,%3};"
        : "+f"(d.x), "+f"(d.y), "+f"(d.z), "+f"(d.w)
        : "r"(__float_as_uint(a[0])), "r"(__float_as_uint(a[1])),
          "r"(__float_as_uint(a[2])), "r"(__float_as_uint(a[3])),
          "r"(__float_as_uint(b[0])), "r"(__float_as_uint(b[1])));
}

// ============ 3xTF32 NT GEMM: C[M,N] = A[M,K] @ B[N,K]^T (+bias) ============
// block 128 thr (4 warps), tile 64x64, warp 32x32, k-tile 32.
// A split into hi/lo tf32 parts; 3 mma per frag pair -> ~fp32 accuracy.
struct GemmBatch {
    const float* A[3];
    const float* Bp[3];
    const float* bias[3];
    float*       C[3];
};

#define GKT 32

__global__ __launch_bounds__(128) void gemm3x(GemmBatch gb, int M, int N, int K, int hasBias) {
    const float* A    = gb.A[blockIdx.z];
    const float* Bp   = gb.Bp[blockIdx.z];
    const float* bias = gb.bias[blockIdx.z];
    float*       C    = gb.C[blockIdx.z];

    __shared__ float Ah[64][36], Al[64][36], Bh[64][36], Bl[64][36];

    int t = threadIdx.x;
    int warp = t >> 5, lane = t & 31;
    int g = lane >> 2, tg = lane & 3;
    int bm = blockIdx.y * 64, bn = blockIdx.x * 64;
    int mbase = (warp & 1) * 32, nbase = (warp >> 1) * 32;

    float4 acc[2][4];
    #pragma unroll
    for (int i = 0; i < 2; i++)
        #pragma unroll
        for (int j = 0; j < 4; j++) acc[i][j] = make_float4(0.f, 0.f, 0.f, 0.f);

    int nkt = (K + GKT - 1) / GKT;
    for (int kt = 0; kt < nkt; kt++) {
        int k0 = kt * GKT;
        #pragma unroll
        for (int i = 0; i < 4; i++) {
            int idx = t + i * 128;        // 0..511
            int row = idx >> 3, s = idx & 7;
            int kk = k0 + s * 4;
            float4 v = make_float4(0.f, 0.f, 0.f, 0.f);
            if (kk + 3 < K) v = *(const float4*)&A[(size_t)(bm + row) * K + kk];
            float h0 = tf32_rna(v.x), h1 = tf32_rna(v.y), h2 = tf32_rna(v.z), h3 = tf32_rna(v.w);
            Ah[row][s*4+0] = h0;      Ah[row][s*4+1] = h1;
            Ah[row][s*4+2] = h2;      Ah[row][s*4+3] = h3;
            Al[row][s*4+0] = v.x - h0; Al[row][s*4+1] = v.y - h1;
            Al[row][s*4+2] = v.z - h2; Al[row][s*4+3] = v.w - h3;

            float4 w = make_float4(0.f, 0.f, 0.f, 0.f);
            if ((bn + row) < N && kk + 3 < K) w = *(const float4*)&Bp[(size_t)(bn + row) * K + kk];
            float q0 = tf32_rna(w.x), q1 = tf32_rna(w.y), q2 = tf32_rna(w.z), q3 = tf32_rna(w.w);
            Bh[row][s*4+0] = q0;      Bh[row][s*4+1] = q1;
            Bh[row][s*4+2] = q2;      Bh[row][s*4+3] = q3;
            Bl[row][s*4+0] = w.x - q0; Bl[row][s*4+1] = w.y - q1;
            Bl[row][s*4+2] = w.z - q2; Bl[row][s*4+3] = w.w - q3;
        }
        __syncthreads();

        #pragma unroll
        for (int ko = 0; ko < GKT; ko += 8) {
            float ah[2][4], al[2][4];
            #pragma unroll
            for (int ms = 0; ms < 2; ms++) {
                int r = mbase + ms * 16;
                ah[ms][0] = Ah[r+g][ko+tg];    ah[ms][1] = Ah[r+g+8][ko+tg];
                ah[ms][2] = Ah[r+g][ko+tg+4];  ah[ms][3] = Ah[r+g+8][ko+tg+4];
                al[ms][0] = Al[r+g][ko+tg];    al[ms][1] = Al[r+g+8][ko+tg];
                al[ms][2] = Al[r+g][ko+tg+4];  al[ms][3] = Al[r+g+8][ko+tg+4];
            }
            #pragma unroll
            for (int ns = 0; ns < 4; ns++) {
                int c = nbase + ns * 8;
                float bh[2], bl[2];
                bh[0] = Bh[c+g][ko+tg];  bh[1] = Bh[c+g][ko+tg+4];
                bl[0] = Bl[c+g][ko+tg];  bl[1] = Bl[c+g][ko+tg+4];
                #pragma unroll
                for (int ms = 0; ms < 2; ms++) {
                    mma_tf32(acc[ms][ns], ah[ms], bh);
                    mma_tf32(acc[ms][ns], al[ms], bh);
                    mma_tf32(acc[ms][ns], ah[ms], bl);
                }
            }
        }
        __syncthreads();
    }

    #pragma unroll
    for (int ms = 0; ms < 2; ms++) {
        #pragma unroll
        for (int ns = 0; ns < 4; ns++) {
            int col = bn + nbase + ns * 8 + 2 * tg;
            if (col < N) {
                float b0 = hasBias ? bias[col]     : 0.f;
                float b1 = hasBias ? bias[col + 1] : 0.f;
                int r0 = bm + mbase + ms * 16 + g;
                float2 v0 = {acc[ms][ns].x + b0, acc[ms][ns].y + b1};
                float2 v1 = {acc[ms][ns].z + b0, acc[ms][ns].w + b1};
                *(float2*)&C[(size_t)r0 * N + col]       = v0;
                *(float2*)&C[(size_t)(r0 + 8) * N + col] = v1;
            }
        }
    }
}

// ============ fused causal attention: QK^T -> exp -> (e out, l, PV) ============
// block 128 thr (4 warps), q-tile 64, k-tile 64, warp 32x32. tf32 mma, rna rounding.
// Writes UNNORMALIZED e to attn (causal region incl. zeroed masked diag entries),
// rowsum l, and normalized Oh. No max subtraction (scores provably small).
__global__ __launch_bounds__(128) void attn_fused(const float* __restrict__ Qp,
                                                  const float* __restrict__ Kp,
                                                  const float* __restrict__ Vp,
                                                  float* __restrict__ attn,
                                                  float* __restrict__ rowsum,
                                                  float* __restrict__ Oh) {
    extern __shared__ float sm[];
    float (*Qs)[68] = (float(*)[68])sm;                 // 64x68
    float (*Es)[68] = (float(*)[68])(sm + 4352);        // 64x68
    float (*Ks)[68] = (float(*)[68])(sm + 8704);        // K view of KV buffer
    float (*Vs)[72] = (float(*)[72])(sm + 8704);        // V view of KV buffer (64x72)
    float* lpart = sm + 8704 + 4608;                    // 4*32
    float* linv  = lpart + 128;                         // 64

    int qt = gridDim.x - 1 - blockIdx.x;   // longest blocks scheduled first
    int bh = blockIdx.y;
    int b = bh >> 4, h = bh & 15;
    int q0 = qt * 64;

    int t = threadIdx.x;
    int warp = t >> 5, lane = t & 31;
    int g = lane >> 2, tg = lane & 3;
    int mbase = (warp & 1) * 32, nbase = (warp >> 1) * 32;

    // load Q tile (rna-rounded)
    #pragma unroll
    for (int i = 0; i < 8; i++) {
        int idx = t + i * 128;
        int row = idx >> 4, s = idx & 15;
        float4 v = *(const float4*)&Qp[(size_t)(b * Sn + q0 + row) * Dn + h * HEADn + s * 4];
        Qs[row][s*4+0] = tf32_rna(v.x); Qs[row][s*4+1] = tf32_rna(v.y);
        Qs[row][s*4+2] = tf32_rna(v.z); Qs[row][s*4+3] = tf32_rna(v.w);
    }

    float4 accp[2][4];
    #pragma unroll
    for (int i = 0; i < 2; i++)
        #pragma unroll
        for (int j = 0; j < 4; j++) accp[i][j] = make_float4(0.f, 0.f, 0.f, 0.f);
    float lacc[4] = {0.f, 0.f, 0.f, 0.f};

    size_t abase = (size_t)bh * Sn * Sn;

    for (int kt = 0; kt <= qt; kt++) {
        int k0 = kt * 64;
        __syncthreads();                      // prior PV reads of KV/Es done
        // load K tile
        #pragma unroll
        for (int i = 0; i < 8; i++) {
            int idx = t + i * 128;
            int row = idx >> 4, s = idx & 15;
            float4 v = *(const float4*)&Kp[(size_t)(b * Sn + k0 + row) * Dn + h * HEADn + s * 4];
            Ks[row][s*4+0] = tf32_rna(v.x); Ks[row][s*4+1] = tf32_rna(v.y);
            Ks[row][s*4+2] = tf32_rna(v.z); Ks[row][s*4+3] = tf32_rna(v.w);
        }
        __syncthreads();

        // QK^T
        float4 accq[2][4];
        #pragma unroll
        for (int i = 0; i < 2; i++)
            #pragma unroll
            for (int j = 0; j < 4; j++) accq[i][j] = make_float4(0.f, 0.f, 0.f, 0.f);

        #pragma unroll
        for (int ko = 0; ko < 64; ko += 8) {
            float a[2][4];
            #pragma unroll
            for (int ms = 0; ms < 2; ms++) {
                int r = mbase + ms * 16;
                a[ms][0] = Qs[r+g][ko+tg];    a[ms][1] = Qs[r+g+8][ko+tg];
                a[ms][2] = Qs[r+g][ko+tg+4];  a[ms][3] = Qs[r+g+8][ko+tg+4];
            }
            #pragma unroll
            for (int ns = 0; ns < 4; ns++) {
                int c = nbase + ns * 8;
                float bb[2];
                bb[0] = Ks[c+g][ko+tg];  bb[1] = Ks[c+g][ko+tg+4];
                #pragma unroll
                for (int ms = 0; ms < 2; ms++) mma_tf32(accq[ms][ns], a[ms], bb);
            }
        }
        __syncthreads();                      // K reads done before V overwrite

        // epilogue: e = exp(s/8), causal mask (only active on diagonal tile)
        #pragma unroll
        for (int ms = 0; ms < 2; ms++) {
            int rlo = mbase + ms * 16 + g;
            int rhi = rlo + 8;
            #pragma unroll
            for (int ns = 0; ns < 4; ns++) {
                int c0 = nbase + ns * 8 + 2 * tg;
                float ex = __expf(accq[ms][ns].x * 0.125f);
                float ey = __expf(accq[ms][ns].y * 0.125f);
                float ez = __expf(accq[ms][ns].z * 0.125f);
                float ew = __expf(accq[ms][ns].w * 0.125f);
                if (k0 + c0     > q0 + rlo) ex = 0.f;
                if (k0 + c0 + 1 > q0 + rlo) ey = 0.f;
                if (k0 + c0     > q0 + rhi) ez = 0.f;
                if (k0 + c0 + 1 > q0 + rhi) ew = 0.f;
                lacc[ms*2+0] += ex + ey;
                lacc[ms*2+1] += ez + ew;
                float2 lo = {ex, ey}, hi = {ez, ew};
                *(float2*)&attn[abase + (size_t)(q0 + rlo) * Sn + k0 + c0] = lo;
                *(float2*)&attn[abase + (size_t)(q0 + rhi) * Sn + k0 + c0] = hi;
                Es[rlo][c0] = tf32_rna(ex); Es[rlo][c0+1] = tf32_rna(ey);
                Es[rhi][c0] = tf32_rna(ez); Es[rhi][c0+1] = tf32_rna(ew);
            }
        }

        // load V tile
        #pragma unroll
        for (int i = 0; i < 8; i++) {
            int idx = t + i * 128;
            int row = idx >> 4, s = idx & 15;
            float4 v = *(const float4*)&Vp[(size_t)(b * Sn + k0 + row) * Dn + h * HEADn + s * 4];
            Vs[row][s*4+0] = tf32_rna(v.x); Vs[row][s*4+1] = tf32_rna(v.y);
            Vs[row][s*4+2] = tf32_rna(v.z); Vs[row][s*4+3] = tf32_rna(v.w);
        }
        __syncthreads();

        // PV
        #pragma unroll
        for (int ko = 0; ko < 64; ko += 8) {
            float a[2][4];
            #pragma unroll
            for (int ms = 0; ms < 2; ms++) {
                int r = mbase + ms * 16;
                a[ms][0] = Es[r+g][ko+tg];    a[ms][1] = Es[r+g+8][ko+tg];
                a[ms][2] = Es[r+g][ko+tg+4];  a[ms][3] = Es[r+g+8][ko+tg+4];
            }
            #pragma unroll
            for (int ns = 0; ns < 4; ns++) {
                int c = nbase + ns * 8;
                float bb[2];
                bb[0] = Vs[ko+tg][c+g];  bb[1] = Vs[ko+tg+4][c+g];
                #pragma unroll
                for (int ms = 0; ms < 2; ms++) mma_tf32(accp[ms][ns], a[ms], bb);
            }
        }
    }

    // reduce l over the 4 tg-lanes sharing each row
    #pragma unroll
    for (int i = 0; i < 4; i++) {
        lacc[i] += __shfl_xor_sync(0xffffffffu, lacc[i], 1);
        lacc[i] += __shfl_xor_sync(0xffffffffu, lacc[i], 2);
    }
    if (tg == 0) {
        #pragma unroll
        for (int ms = 0; ms < 2; ms++) {
            lpart[warp * 32 + ms * 16 + g]     = lacc[ms*2+0];
            lpart[warp * 32 + ms * 16 + 8 + g] = lacc[ms*2+1];
        }
    }
    __syncthreads();
    if (t < 64) {
        float l = (t < 32) ? (lpart[t] + lpart[64 + t])
                           : (lpart[32 + (t - 32)] + lpart[96 + (t - 32)]);
        rowsum[bh * Sn + q0 + t] = l;
        linv[t] = 1.f / l;
    }
    __syncthreads();

    // normalized O tile (merged-head layout [B,S,D])
    #pragma unroll
    for (int ms = 0; ms < 2; ms++) {
        int rlo = mbase + ms * 16 + g;
        int rhi = rlo + 8;
        float ilo = linv[rlo], ihi = linv[rhi];
        #pragma unroll
        for (int ns = 0; ns < 4; ns++) {
            int c0 = nbase + ns * 8 + 2 * tg;
            float2 lo = {accp[ms][ns].x * ilo, accp[ms][ns].y * ilo};
            float2 hi = {accp[ms][ns].z * ihi, accp[ms][ns].w * ihi};
            *(float2*)&Oh[(size_t)(b * Sn + q0 + rlo) * Dn + h * HEADn + c0] = lo;
            *(float2*)&Oh[(size_t)(b * Sn + q0 + rhi) * Dn + h * HEADn + c0] = hi;
        }
    }
}

// ============ normalize attn rows + zero-fill upper triangle ============
__global__ __launch_bounds__(256) void attn_norm(float* __restrict__ attn,
                                                 const float* __restrict__ rowsum) {
    int q = blockIdx.x, bh = blockIdx.y;
    float inv = 1.f / rowsum[bh * Sn + q];
    int n = ((q >> 6) + 1) * 64;
    size_t base = (size_t)bh * Sn * Sn + (size_t)q * Sn;
    for (int k = threadIdx.x * 4; k < Sn; k += 256 * 4) {
        if (k < n) {
            float4 v = *(float4*)&attn[base + k];
            v.x *= inv; v.y *= inv; v.z *= inv; v.w *= inv;
            *(float4*)&attn[base + k] = v;
        } else {
            *(float4*)&attn[base + k] = make_float4(0.f, 0.f, 0.f, 0.f);
        }
    }
}

// ---------------- launch ----------------
extern "C" void kernel_launch(void* const* d_in, const int* in_sizes, int n_in,
                              void* d_out, int out_size) {
    (void)in_sizes; (void)n_in; (void)out_size;

    const float* q  = (const float*)d_in[0];
    const float* k  = (const float*)d_in[1];
    const float* v  = (const float*)d_in[2];
    const float* Vq = (const float*)d_in[3];
    const float* Uq = (const float*)d_in[4];
    const float* bq = (const float*)d_in[5];
    const float* Vk = (const float*)d_in[6];
    const float* Uk = (const float*)d_in[7];
    const float* bk = (const float*)d_in[8];
    const float* Vv = (const float*)d_in[9];
    const float* Uv = (const float*)d_in[10];
    const float* bv = (const float*)d_in[11];
    const float* Vo = (const float*)d_in[12];
    const float* Uo = (const float*)d_in[13];
    const float* bo = (const float*)d_in[14];

    float* out  = (float*)d_out;
    float* attn = out + (size_t)Mn * Dn;

    void *p_tmp, *p_q, *p_k, *p_v, *p_oh, *p_rs;
    cudaGetSymbolAddress(&p_tmp, g_tmp);
    cudaGetSymbolAddress(&p_q, g_qp);
    cudaGetSymbolAddress(&p_k, g_kp);
    cudaGetSymbolAddress(&p_v, g_vp);
    cudaGetSymbolAddress(&p_oh, g_oh);
    cudaGetSymbolAddress(&p_rs, g_rowsum);

    float* tmp0 = (float*)p_tmp;
    float* tmp1 = tmp0 + (size_t)Mn * RANKn;
    float* tmp2 = tmp1 + (size_t)Mn * RANKn;
    float* gq = (float*)p_q;
    float* gk = (float*)p_k;
    float* gv = (float*)p_v;
    float* goh = (float*)p_oh;
    float* grs = (float*)p_rs;

    const int ATTN_SMEM = (4352 * 2 + 4608 + 128 + 64) * 4;   // 54016 B
    cudaFuncSetAttribute(attn_fused, cudaFuncAttributeMaxDynamicSharedMemorySize, ATTN_SMEM);

    // 1) down-projection q,k,v: tmp = x @ V^T  [4096,204]
    GemmBatch g1;
    g1.A[0] = q;  g1.A[1] = k;  g1.A[2] = v;
    g1.Bp[0] = Vq; g1.Bp[1] = Vk; g1.Bp[2] = Vv;
    g1.bias[0] = g1.bias[1] = g1.bias[2] = nullptr;
    g1.C[0] = tmp0; g1.C[1] = tmp1; g1.C[2] = tmp2;
    gemm3x<<<dim3((RANKn + 63) / 64, Mn / 64, 3), 128>>>(g1, Mn, RANKn, Dn, 0);

    // 2) up-projection: proj = tmp @ U^T + b  [4096,1024]
    GemmBatch g2;
    g2.A[0] = tmp0; g2.A[1] = tmp1; g2.A[2] = tmp2;
    g2.Bp[0] = Uq; g2.Bp[1] = Uk; g2.Bp[2] = Uv;
    g2.bias[0] = bq; g2.bias[1] = bk; g2.bias[2] = bv;
    g2.C[0] = gq; g2.C[1] = gk; g2.C[2] = gv;
    gemm3x<<<dim3(Dn / 64, Mn / 64, 3), 128>>>(g2, Mn, Dn, RANKn, 1);

    // 3) fused attention + normalization
    attn_fused<<<dim3(Sn / 64, BHn), 128, ATTN_SMEM>>>(gq, gk, gv, attn, grs, goh);
    attn_norm<<<dim3(Sn, BHn), 256>>>(attn, grs);

    // 4) output projection
    GemmBatch g3;
    g3.A[0] = goh; g3.Bp[0] = Vo; g3.bias[0] = nullptr; g3.C[0] = tmp0;
    g3.A[1] = g3.A[2] = nullptr; g3.Bp[1] = g3.Bp[2] = nullptr;
    g3.bias[1] = g3.bias[2] = nullptr; g3.C[1] = g3.C[2] = nullptr;
    gemm3x<<<dim3((RANKn + 63) / 64, Mn / 64, 1), 128>>>(g3, Mn, RANKn, Dn, 0);

    GemmBatch g4;
    g4.A[0] = tmp0; g4.Bp[0] = Uo; g4.bias[0] = bo; g4.C[0] = out;
    g4.A[1] = g4.A[2] = nullptr; g4.Bp[1] = g4.Bp[2] = nullptr;
    g4.bias[1] = g4.bias[2] = nullptr; g4.C[1] = g4.C[2] = nullptr;
    gemm3x<<<dim3(Dn / 64, Mn / 64, 1), 128>>>(g4, Mn, Dn, RANKn, 1);
}

// round 3
// speedup vs baseline: 2.8782x; 1.3248x over previous
#include <cuda_runtime.h>
#include <math.h>

#define Bn    2
#define Sn    2048
#define Dn    1024
#define Hn    16
#define HEADn 64
#define RANKn 204
#define BHn   (Bn*Hn)
#define Mn    (Bn*Sn)

// ---------------- scratch ----------------
__device__ float g_tmp[3][(size_t)Mn*RANKn];
__device__ float g_qp[(size_t)Mn*Dn];
__device__ float g_kp[(size_t)Mn*Dn];
__device__ float g_vp[(size_t)Mn*Dn];
__device__ float g_oh[(size_t)Mn*Dn];

// ---------------- helpers ----------------
__device__ __forceinline__ float tf32_rna(float a) {
    unsigned r;
    asm("cvt.rna.tf32.f32 %0, %1;" : "=r"(r) : "f"(a));
    return __uint_as_float(r);
}

__device__ __forceinline__ void mma_tf32(float4& d, const float* a, const float* b) {
    asm volatile(
        "mma.sync.aligned.m16n8k8.row.col.f32.tf32.tf32.f32 "
        "{%0,%1,%2,%3},{%4,%5,%6,%7},{%8,%9},{%0,%1,%2,%3};"
        : "+f"(d.x), "+f"(d.y), "+f"(d.z), "+f"(d.w)
        : "r"(__float_as_uint(a[0])), "r"(__float_as_uint(a[1])),
          "r"(__float_as_uint(a[2])), "r"(__float_as_uint(a[3])),
          "r"(__float_as_uint(b[0])), "r"(__float_as_uint(b[1])));
}

// ============ 3xTF32 NT GEMM with k-pipeline: C = A @ B^T (+bias) ============
struct GemmBatch {
    const float* A[3];
    const float* Bp[3];
    const float* bias[3];
    float*       C[3];
};

#define GKT 32

__global__ __launch_bounds__(128) void gemm3x(GemmBatch gb, int M, int N, int K, int hasBias) {
    const float* A    = gb.A[blockIdx.z];
    const float* Bp   = gb.Bp[blockIdx.z];
    const float* bias = gb.bias[blockIdx.z];
    float*       C    = gb.C[blockIdx.z];

    __shared__ float Ah[64][36], Al[64][36], Bh[64][36], Bl[64][36];

    int t = threadIdx.x;
    int warp = t >> 5, lane = t & 31;
    int g = lane >> 2, tg = lane & 3;
    int bm = blockIdx.y * 64, bn = blockIdx.x * 64;
    int mbase = (warp & 1) * 32, nbase = (warp >> 1) * 32;

    // per-thread gmem slots: idx = t + i*128 -> row = idx>>3 (0..63), s = idx&7
    int lrow[4], lsc[4];
    #pragma unroll
    for (int i = 0; i < 4; i++) { int idx = t + i * 128; lrow[i] = idx >> 3; lsc[i] = idx & 7; }

    float4 ra[4], rb[4];
    auto fetch = [&](int k0) {
        #pragma unroll
        for (int i = 0; i < 4; i++) {
            int kk = k0 + lsc[i] * 4;
            ra[i] = make_float4(0.f, 0.f, 0.f, 0.f);
            rb[i] = make_float4(0.f, 0.f, 0.f, 0.f);
            if (kk + 3 < K) {
                ra[i] = *(const float4*)&A[(size_t)(bm + lrow[i]) * K + kk];
                if ((bn + lrow[i]) < N) rb[i] = *(const float4*)&Bp[(size_t)(bn + lrow[i]) * K + kk];
            }
        }
    };

    float4 acc[2][4];
    #pragma unroll
    for (int i = 0; i < 2; i++)
        #pragma unroll
        for (int j = 0; j < 4; j++) acc[i][j] = make_float4(0.f, 0.f, 0.f, 0.f);

    int nkt = (K + GKT - 1) / GKT;
    fetch(0);

    for (int kt = 0; kt < nkt; kt++) {
        // store staged tile into smem (hi/lo split)
        #pragma unroll
        for (int i = 0; i < 4; i++) {
            int row = lrow[i], s = lsc[i];
            float4 v = ra[i];
            float h0 = tf32_rna(v.x), h1 = tf32_rna(v.y), h2 = tf32_rna(v.z), h3 = tf32_rna(v.w);
            Ah[row][s*4+0] = h0;       Ah[row][s*4+1] = h1;
            Ah[row][s*4+2] = h2;       Ah[row][s*4+3] = h3;
            Al[row][s*4+0] = v.x - h0; Al[row][s*4+1] = v.y - h1;
            Al[row][s*4+2] = v.z - h2; Al[row][s*4+3] = v.w - h3;
            float4 w = rb[i];
            float q0 = tf32_rna(w.x), q1 = tf32_rna(w.y), q2 = tf32_rna(w.z), q3 = tf32_rna(w.w);
            Bh[row][s*4+0] = q0;       Bh[row][s*4+1] = q1;
            Bh[row][s*4+2] = q2;       Bh[row][s*4+3] = q3;
            Bl[row][s*4+0] = w.x - q0; Bl[row][s*4+1] = w.y - q1;
            Bl[row][s*4+2] = w.z - q2; Bl[row][s*4+3] = w.w - q3;
        }
        __syncthreads();

        if (kt + 1 < nkt) fetch((kt + 1) * GKT);   // prefetch overlaps mma

        #pragma unroll
        for (int ko = 0; ko < GKT; ko += 8) {
            float ah[2][4], al[2][4];
            #pragma unroll
            for (int ms = 0; ms < 2; ms++) {
                int r = mbase + ms * 16;
                ah[ms][0] = Ah[r+g][ko+tg];    ah[ms][1] = Ah[r+g+8][ko+tg];
                ah[ms][2] = Ah[r+g][ko+tg+4];  ah[ms][3] = Ah[r+g+8][ko+tg+4];
                al[ms][0] = Al[r+g][ko+tg];    al[ms][1] = Al[r+g+8][ko+tg];
                al[ms][2] = Al[r+g][ko+tg+4];  al[ms][3] = Al[r+g+8][ko+tg+4];
            }
            #pragma unroll
            for (int ns = 0; ns < 4; ns++) {
                int c = nbase + ns * 8;
                float bh[2], bl[2];
                bh[0] = Bh[c+g][ko+tg];  bh[1] = Bh[c+g][ko+tg+4];
                bl[0] = Bl[c+g][ko+tg];  bl[1] = Bl[c+g][ko+tg+4];
                #pragma unroll
                for (int ms = 0; ms < 2; ms++) {
                    mma_tf32(acc[ms][ns], ah[ms], bh);
                    mma_tf32(acc[ms][ns], al[ms], bh);
                    mma_tf32(acc[ms][ns], ah[ms], bl);
                }
            }
        }
        __syncthreads();
    }

    #pragma unroll
    for (int ms = 0; ms < 2; ms++) {
        #pragma unroll
        for (int ns = 0; ns < 4; ns++) {
            int col = bn + nbase + ns * 8 + 2 * tg;
            if (col < N) {
                float b0 = hasBias ? bias[col]     : 0.f;
                float b1 = hasBias ? bias[col + 1] : 0.f;
                int r0 = bm + mbase + ms * 16 + g;
                float2 v0 = {acc[ms][ns].x + b0, acc[ms][ns].y + b1};
                float2 v1 = {acc[ms][ns].z + b0, acc[ms][ns].w + b1};
                *(float2*)&C[(size_t)r0 * N + col]       = v0;
                *(float2*)&C[(size_t)(r0 + 8) * N + col] = v1;
            }
        }
    }
}

// ============ fully fused causal attention ============
// Loop 1: QK^T -> exp -> l, PV  (no attn writes)
// Loop 2: recompute QK^T (bitwise identical), exp * (1/l), write normalized attn;
//         upper-triangle tiles written as zeros. attn_norm kernel eliminated.
__global__ __launch_bounds__(128) void attn_fused(const float* __restrict__ Qp,
                                                  const float* __restrict__ Kp,
                                                  const float* __restrict__ Vp,
                                                  float* __restrict__ attn,
                                                  float* __restrict__ Oh) {
    extern __shared__ float sm[];
    float (*Qs)[68] = (float(*)[68])sm;                 // 64x68
    float (*Es)[68] = (float(*)[68])(sm + 4352);        // 64x68
    float (*Ks)[68] = (float(*)[68])(sm + 8704);        // 64x68
    float (*Vs)[72] = (float(*)[72])(sm + 13056);       // 64x72
    float* lpart = sm + 17664;                          // 128
    float* linv  = lpart + 128;                         // 64

    int qt = gridDim.x - 1 - blockIdx.x;
    int bh = blockIdx.y;
    int b = bh >> 4, h = bh & 15;
    int q0 = qt * 64;

    int t = threadIdx.x;
    int warp = t >> 5, lane = t & 31;
    int g = lane >> 2, tg = lane & 3;
    int mbase = (warp & 1) * 32, nbase = (warp >> 1) * 32;

    // load Q tile (rna-rounded) — stays resident for both loops
    #pragma unroll
    for (int i = 0; i < 8; i++) {
        int idx = t + i * 128;
        int row = idx >> 4, s = idx & 15;
        float4 v = *(const float4*)&Qp[(size_t)(b * Sn + q0 + row) * Dn + h * HEADn + s * 4];
        Qs[row][s*4+0] = tf32_rna(v.x); Qs[row][s*4+1] = tf32_rna(v.y);
        Qs[row][s*4+2] = tf32_rna(v.z); Qs[row][s*4+3] = tf32_rna(v.w);
    }

    float4 accp[2][4];
    #pragma unroll
    for (int i = 0; i < 2; i++)
        #pragma unroll
        for (int j = 0; j < 4; j++) accp[i][j] = make_float4(0.f, 0.f, 0.f, 0.f);
    float lacc[4] = {0.f, 0.f, 0.f, 0.f};

    size_t abase = (size_t)bh * Sn * Sn;

    // ---------------- loop 1: l and PV ----------------
    for (int kt = 0; kt <= qt; kt++) {
        int k0 = kt * 64;
        #pragma unroll
        for (int i = 0; i < 8; i++) {
            int idx = t + i * 128;
            int row = idx >> 4, s = idx & 15;
            float4 v = *(const float4*)&Kp[(size_t)(b * Sn + k0 + row) * Dn + h * HEADn + s * 4];
            Ks[row][s*4+0] = tf32_rna(v.x); Ks[row][s*4+1] = tf32_rna(v.y);
            Ks[row][s*4+2] = tf32_rna(v.z); Ks[row][s*4+3] = tf32_rna(v.w);
        }
        __syncthreads();

        float4 accq[2][4];
        #pragma unroll
        for (int i = 0; i < 2; i++)
            #pragma unroll
            for (int j = 0; j < 4; j++) accq[i][j] = make_float4(0.f, 0.f, 0.f, 0.f);

        #pragma unroll
        for (int ko = 0; ko < 64; ko += 8) {
            float a[2][4];
            #pragma unroll
            for (int ms = 0; ms < 2; ms++) {
                int r = mbase + ms * 16;
                a[ms][0] = Qs[r+g][ko+tg];    a[ms][1] = Qs[r+g+8][ko+tg];
                a[ms][2] = Qs[r+g][ko+tg+4];  a[ms][3] = Qs[r+g+8][ko+tg+4];
            }
            #pragma unroll
            for (int ns = 0; ns < 4; ns++) {
                int c = nbase + ns * 8;
                float bb[2];
                bb[0] = Ks[c+g][ko+tg];  bb[1] = Ks[c+g][ko+tg+4];
                #pragma unroll
                for (int ms = 0; ms < 2; ms++) mma_tf32(accq[ms][ns], a[ms], bb);
            }
        }

        // epilogue: e = exp(s/8), causal mask, stage into Es
        #pragma unroll
        for (int ms = 0; ms < 2; ms++) {
            int rlo = mbase + ms * 16 + g;
            int rhi = rlo + 8;
            #pragma unroll
            for (int ns = 0; ns < 4; ns++) {
                int c0 = nbase + ns * 8 + 2 * tg;
                float ex = __expf(accq[ms][ns].x * 0.125f);
                float ey = __expf(accq[ms][ns].y * 0.125f);
                float ez = __expf(accq[ms][ns].z * 0.125f);
                float ew = __expf(accq[ms][ns].w * 0.125f);
                if (k0 + c0     > q0 + rlo) ex = 0.f;
                if (k0 + c0 + 1 > q0 + rlo) ey = 0.f;
                if (k0 + c0     > q0 + rhi) ez = 0.f;
                if (k0 + c0 + 1 > q0 + rhi) ew = 0.f;
                lacc[ms*2+0] += ex + ey;
                lacc[ms*2+1] += ez + ew;
                Es[rlo][c0] = tf32_rna(ex); Es[rlo][c0+1] = tf32_rna(ey);
                Es[rhi][c0] = tf32_rna(ez); Es[rhi][c0+1] = tf32_rna(ew);
            }
        }

        // load V tile
        #pragma unroll
        for (int i = 0; i < 8; i++) {
            int idx = t + i * 128;
            int row = idx >> 4, s = idx & 15;
            float4 v = *(const float4*)&Vp[(size_t)(b * Sn + k0 + row) * Dn + h * HEADn + s * 4];
            Vs[row][s*4+0] = tf32_rna(v.x); Vs[row][s*4+1] = tf32_rna(v.y);
            Vs[row][s*4+2] = tf32_rna(v.z); Vs[row][s*4+3] = tf32_rna(v.w);
        }
        __syncthreads();

        // PV
        #pragma unroll
        for (int ko = 0; ko < 64; ko += 8) {
            float a[2][4];
            #pragma unroll
            for (int ms = 0; ms < 2; ms++) {
                int r = mbase + ms * 16;
                a[ms][0] = Es[r+g][ko+tg];    a[ms][1] = Es[r+g+8][ko+tg];
                a[ms][2] = Es[r+g][ko+tg+4];  a[ms][3] = Es[r+g+8][ko+tg+4];
            }
            #pragma unroll
            for (int ns = 0; ns < 4; ns++) {
                int c = nbase + ns * 8;
                float bb[2];
                bb[0] = Vs[ko+tg][c+g];  bb[1] = Vs[ko+tg+4][c+g];
                #pragma unroll
                for (int ms = 0; ms < 2; ms++) mma_tf32(accp[ms][ns], a[ms], bb);
            }
        }
    }

    // ---------------- row sums -> linv ----------------
    #pragma unroll
    for (int i = 0; i < 4; i++) {
        lacc[i] += __shfl_xor_sync(0xffffffffu, lacc[i], 1);
        lacc[i] += __shfl_xor_sync(0xffffffffu, lacc[i], 2);
    }
    if (tg == 0) {
        #pragma unroll
        for (int ms = 0; ms < 2; ms++) {
            lpart[warp * 32 + ms * 16 + g]     = lacc[ms*2+0];
            lpart[warp * 32 + ms * 16 + 8 + g] = lacc[ms*2+1];
        }
    }
    __syncthreads();
    if (t < 64) {
        float l = (t < 32) ? (lpart[t] + lpart[64 + t])
                           : (lpart[32 + (t - 32)] + lpart[96 + (t - 32)]);
        linv[t] = 1.f / l;
    }
    __syncthreads();

    // normalized O tile (merged-head layout [B,S,D])
    #pragma unroll
    for (int ms = 0; ms < 2; ms++) {
        int rlo = mbase + ms * 16 + g;
        int rhi = rlo + 8;
        float ilo = linv[rlo], ihi = linv[rhi];
        #pragma unroll
        for (int ns = 0; ns < 4; ns++) {
            int c0 = nbase + ns * 8 + 2 * tg;
            float2 lo = {accp[ms][ns].x * ilo, accp[ms][ns].y * ilo};
            float2 hi = {accp[ms][ns].z * ihi, accp[ms][ns].w * ihi};
            *(float2*)&Oh[(size_t)(b * Sn + q0 + rlo) * Dn + h * HEADn + c0] = lo;
            *(float2*)&Oh[(size_t)(b * Sn + q0 + rhi) * Dn + h * HEADn + c0] = hi;
        }
    }

    // ---------------- loop 2: recompute scores, write normalized attn ----------------
    for (int kt = 0; kt < Sn / 64; kt++) {
        int k0 = kt * 64;
        if (kt <= qt) {
            __syncthreads();   // previous iter's QK reads of Ks complete
            #pragma unroll
            for (int i = 0; i < 8; i++) {
                int idx = t + i * 128;
                int row = idx >> 4, s = idx & 15;
                float4 v = *(const float4*)&Kp[(size_t)(b * Sn + k0 + row) * Dn + h * HEADn + s * 4];
                Ks[row][s*4+0] = tf32_rna(v.x); Ks[row][s*4+1] = tf32_rna(v.y);
                Ks[row][s*4+2] = tf32_rna(v.z); Ks[row][s*4+3] = tf32_rna(v.w);
            }
            __syncthreads();

            float4 accq[2][4];
            #pragma unroll
            for (int i = 0; i < 2; i++)
                #pragma unroll
                for (int j = 0; j < 4; j++) accq[i][j] = make_float4(0.f, 0.f, 0.f, 0.f);

            #pragma unroll
            for (int ko = 0; ko < 64; ko += 8) {
                float a[2][4];
                #pragma unroll
                for (int ms = 0; ms < 2; ms++) {
                    int r = mbase + ms * 16;
                    a[ms][0] = Qs[r+g][ko+tg];    a[ms][1] = Qs[r+g+8][ko+tg];
                    a[ms][2] = Qs[r+g][ko+tg+4];  a[ms][3] = Qs[r+g+8][ko+tg+4];
                }
                #pragma unroll
                for (int ns = 0; ns < 4; ns++) {
                    int c = nbase + ns * 8;
                    float bb[2];
                    bb[0] = Ks[c+g][ko+tg];  bb[1] = Ks[c+g][ko+tg+4];
                    #pragma unroll
                    for (int ms = 0; ms < 2; ms++) mma_tf32(accq[ms][ns], a[ms], bb);
                }
            }

            #pragma unroll
            for (int ms = 0; ms < 2; ms++) {
                int rlo = mbase + ms * 16 + g;
                int rhi = rlo + 8;
                float ilo = linv[rlo], ihi = linv[rhi];
                #pragma unroll
                for (int ns = 0; ns < 4; ns++) {
                    int c0 = nbase + ns * 8 + 2 * tg;
                    float ex = __expf(accq[ms][ns].x * 0.125f);
                    float ey = __expf(accq[ms][ns].y * 0.125f);
                    float ez = __expf(accq[ms][ns].z * 0.125f);
                    float ew = __expf(accq[ms][ns].w * 0.125f);
                    if (k0 + c0     > q0 + rlo) ex = 0.f;
                    if (k0 + c0 + 1 > q0 + rlo) ey = 0.f;
                    if (k0 + c0     > q0 + rhi) ez = 0.f;
                    if (k0 + c0 + 1 > q0 + rhi) ew = 0.f;
                    float2 lo = {ex * ilo, ey * ilo};
                    float2 hi = {ez * ihi, ew * ihi};
                    *(float2*)&attn[abase + (size_t)(q0 + rlo) * Sn + k0 + c0] = lo;
                    *(float2*)&attn[abase + (size_t)(q0 + rhi) * Sn + k0 + c0] = hi;
                }
            }
        } else {
            // fully masked tile: zeros
            float4 z4 = make_float4(0.f, 0.f, 0.f, 0.f);
            #pragma unroll
            for (int i = 0; i < 8; i++) {
                int idx = t + i * 128;
                int row = idx >> 4, c4 = idx & 15;
                *(float4*)&attn[abase + (size_t)(q0 + row) * Sn + k0 + c4 * 4] = z4;
            }
        }
    }
}

// ---------------- launch ----------------
extern "C" void kernel_launch(void* const* d_in, const int* in_sizes, int n_in,
                              void* d_out, int out_size) {
    (void)in_sizes; (void)n_in; (void)out_size;

    const float* q  = (const float*)d_in[0];
    const float* k  = (const float*)d_in[1];
    const float* v  = (const float*)d_in[2];
    const float* Vq = (const float*)d_in[3];
    const float* Uq = (const float*)d_in[4];
    const float* bq = (const float*)d_in[5];
    const float* Vk = (const float*)d_in[6];
    const float* Uk = (const float*)d_in[7];
    const float* bk = (const float*)d_in[8];
    const float* Vv = (const float*)d_in[9];
    const float* Uv = (const float*)d_in[10];
    const float* bv = (const float*)d_in[11];
    const float* Vo = (const float*)d_in[12];
    const float* Uo = (const float*)d_in[13];
    const float* bo = (const float*)d_in[14];

    float* out  = (float*)d_out;
    float* attn = out + (size_t)Mn * Dn;

    void *p_tmp, *p_q, *p_k, *p_v, *p_oh;
    cudaGetSymbolAddress(&p_tmp, g_tmp);
    cudaGetSymbolAddress(&p_q, g_qp);
    cudaGetSymbolAddress(&p_k, g_kp);
    cudaGetSymbolAddress(&p_v, g_vp);
    cudaGetSymbolAddress(&p_oh, g_oh);

    float* tmp0 = (float*)p_tmp;
    float* tmp1 = tmp0 + (size_t)Mn * RANKn;
    float* tmp2 = tmp1 + (size_t)Mn * RANKn;
    float* gq = (float*)p_q;
    float* gk = (float*)p_k;
    float* gv = (float*)p_v;
    float* goh = (float*)p_oh;

    const int ATTN_SMEM = (4352 * 3 + 4608 + 128 + 64) * 4;   // 71424 B
    cudaFuncSetAttribute(attn_fused, cudaFuncAttributeMaxDynamicSharedMemorySize, ATTN_SMEM);

    // 1) down-projection q,k,v
    GemmBatch g1;
    g1.A[0] = q;  g1.A[1] = k;  g1.A[2] = v;
    g1.Bp[0] = Vq; g1.Bp[1] = Vk; g1.Bp[2] = Vv;
    g1.bias[0] = g1.bias[1] = g1.bias[2] = nullptr;
    g1.C[0] = tmp0; g1.C[1] = tmp1; g1.C[2] = tmp2;
    gemm3x<<<dim3((RANKn + 63) / 64, Mn / 64, 3), 128>>>(g1, Mn, RANKn, Dn, 0);

    // 2) up-projection
    GemmBatch g2;
    g2.A[0] = tmp0; g2.A[1] = tmp1; g2.A[2] = tmp2;
    g2.Bp[0] = Uq; g2.Bp[1] = Uk; g2.Bp[2] = Uv;
    g2.bias[0] = bq; g2.bias[1] = bk; g2.bias[2] = bv;
    g2.C[0] = gq; g2.C[1] = gk; g2.C[2] = gv;
    gemm3x<<<dim3(Dn / 64, Mn / 64, 3), 128>>>(g2, Mn, Dn, RANKn, 1);

    // 3) fully fused attention (writes normalized attn directly)
    attn_fused<<<dim3(Sn / 64, BHn), 128, ATTN_SMEM>>>(gq, gk, gv, attn, goh);

    // 4) output projection
    GemmBatch g3;
    g3.A[0] = goh; g3.Bp[0] = Vo; g3.bias[0] = nullptr; g3.C[0] = tmp0;
    g3.A[1] = g3.A[2] = nullptr; g3.Bp[1] = g3.Bp[2] = nullptr;
    g3.bias[1] = g3.bias[2] = nullptr; g3.C[1] = g3.C[2] = nullptr;
    gemm3x<<<dim3((RANKn + 63) / 64, Mn / 64, 1), 128>>>(g3, Mn, RANKn, Dn, 0);

    GemmBatch g4;
    g4.A[0] = tmp0; g4.Bp[0] = Uo; g4.bias[0] = bo; g4.C[0] = out;
    g4.A[1] = g4.A[2] = nullptr; g4.Bp[1] = g4.Bp[2] = nullptr;
    g4.bias[1] = g4.bias[2] = nullptr; g4.C[1] = g4.C[2] = nullptr;
    gemm3x<<<dim3(Dn / 64, Mn / 64, 1), 128>>>(g4, Mn, Dn, RANKn, 1);
}

// round 4
// speedup vs baseline: 3.5135x; 1.2207x over previous
#include <cuda_runtime.h>
#include <math.h>

#define Bn    2
#define Sn    2048
#define Dn    1024
#define Hn    16
#define HEADn 64
#define RANKn 204
#define BHn   (Bn*Hn)
#define Mn    (Bn*Sn)

// ---------------- scratch ----------------
__device__ float g_tmp[3][(size_t)Mn*RANKn];
__device__ float g_split[4][(size_t)Mn*RANKn];   // split-K partials for g3
__device__ float g_qp[(size_t)Mn*Dn];
__device__ float g_kp[(size_t)Mn*Dn];
__device__ float g_vp[(size_t)Mn*Dn];
__device__ float g_oh[(size_t)Mn*Dn];

// ---------------- helpers ----------------
__device__ __forceinline__ float tf32_rna(float a) {
    unsigned r;
    asm("cvt.rna.tf32.f32 %0, %1;" : "=r"(r) : "f"(a));
    return __uint_as_float(r);
}

__device__ __forceinline__ void mma_tf32(float4& d, const float* a, const float* b) {
    asm volatile(
        "mma.sync.aligned.m16n8k8.row.col.f32.tf32.tf32.f32 "
        "{%0,%1,%2,%3},{%4,%5,%6,%7},{%8,%9},{%0,%1,%2,%3};"
        : "+f"(d.x), "+f"(d.y), "+f"(d.z), "+f"(d.w)
        : "r"(__float_as_uint(a[0])), "r"(__float_as_uint(a[1])),
          "r"(__float_as_uint(a[2])), "r"(__float_as_uint(a[3])),
          "r"(__float_as_uint(b[0])), "r"(__float_as_uint(b[1])));
}

// ============ 1xTF32 NT GEMM with k-pipeline, split-K, partial-sum A ============
struct GemmBatch {
    const float* A[3];
    const float* Bp[3];
    const float* bias[3];
    float*       C[3];
};

#define GKT 32

// ksplit>1: blockIdx.z = K-slice (slot 0 only), C offset by slice*cstride.
// sumA>0:  A is base of sumA consecutive partial buffers (stride astride), summed on load.
__global__ __launch_bounds__(128) void gemm1x(GemmBatch gb, int M, int N, int K,
                                              int hasBias, int ksplit, size_t cstride,
                                              int sumA, size_t astride) {
    int z = blockIdx.z;
    int batch = (ksplit > 1) ? 0 : z;
    int slice = (ksplit > 1) ? z : 0;
    int Klen  = K / ksplit;

    const float* A    = gb.A[batch] + (size_t)slice * Klen;
    const float* Bp   = gb.Bp[batch] + (size_t)slice * Klen;
    const float* bias = gb.bias[batch];
    float*       C    = gb.C[batch] + (size_t)slice * cstride;

    __shared__ float Ah[64][36], Bh[64][36];

    int t = threadIdx.x;
    int warp = t >> 5, lane = t & 31;
    int g = lane >> 2, tg = lane & 3;
    int bm = blockIdx.y * 64, bn = blockIdx.x * 64;
    int mbase = (warp & 1) * 32, nbase = (warp >> 1) * 32;

    int lrow[4], lsc[4];
    #pragma unroll
    for (int i = 0; i < 4; i++) { int idx = t + i * 128; lrow[i] = idx >> 3; lsc[i] = idx & 7; }

    float4 ra[4], rb[4];
    auto fetch = [&](int k0) {
        #pragma unroll
        for (int i = 0; i < 4; i++) {
            int kk = k0 + lsc[i] * 4;
            ra[i] = make_float4(0.f, 0.f, 0.f, 0.f);
            rb[i] = make_float4(0.f, 0.f, 0.f, 0.f);
            if (kk + 3 < Klen) {
                size_t aoff = (size_t)(bm + lrow[i]) * K + kk;
                if (sumA) {
                    #pragma unroll
                    for (int p = 0; p < 4; p++) {
                        float4 v = *(const float4*)&A[p * astride + aoff];
                        ra[i].x += v.x; ra[i].y += v.y; ra[i].z += v.z; ra[i].w += v.w;
                    }
                } else {
                    ra[i] = *(const float4*)&A[aoff];
                }
                if ((bn + lrow[i]) < N) rb[i] = *(const float4*)&Bp[(size_t)(bn + lrow[i]) * K + kk];
            }
        }
    };

    float4 acc[2][4];
    #pragma unroll
    for (int i = 0; i < 2; i++)
        #pragma unroll
        for (int j = 0; j < 4; j++) acc[i][j] = make_float4(0.f, 0.f, 0.f, 0.f);

    int nkt = (Klen + GKT - 1) / GKT;
    fetch(0);

    for (int kt = 0; kt < nkt; kt++) {
        #pragma unroll
        for (int i = 0; i < 4; i++) {
            int row = lrow[i], s = lsc[i];
            float4 v = ra[i];
            Ah[row][s*4+0] = tf32_rna(v.x); Ah[row][s*4+1] = tf32_rna(v.y);
            Ah[row][s*4+2] = tf32_rna(v.z); Ah[row][s*4+3] = tf32_rna(v.w);
            float4 w = rb[i];
            Bh[row][s*4+0] = tf32_rna(w.x); Bh[row][s*4+1] = tf32_rna(w.y);
            Bh[row][s*4+2] = tf32_rna(w.z); Bh[row][s*4+3] = tf32_rna(w.w);
        }
        __syncthreads();

        if (kt + 1 < nkt) fetch((kt + 1) * GKT);   // prefetch overlaps mma

        #pragma unroll
        for (int ko = 0; ko < GKT; ko += 8) {
            float ah[2][4];
            #pragma unroll
            for (int ms = 0; ms < 2; ms++) {
                int r = mbase + ms * 16;
                ah[ms][0] = Ah[r+g][ko+tg];    ah[ms][1] = Ah[r+g+8][ko+tg];
                ah[ms][2] = Ah[r+g][ko+tg+4];  ah[ms][3] = Ah[r+g+8][ko+tg+4];
            }
            #pragma unroll
            for (int ns = 0; ns < 4; ns++) {
                int c = nbase + ns * 8;
                float bb[2];
                bb[0] = Bh[c+g][ko+tg];  bb[1] = Bh[c+g][ko+tg+4];
                #pragma unroll
                for (int ms = 0; ms < 2; ms++) mma_tf32(acc[ms][ns], ah[ms], bb);
            }
        }
        __syncthreads();
    }

    #pragma unroll
    for (int ms = 0; ms < 2; ms++) {
        #pragma unroll
        for (int ns = 0; ns < 4; ns++) {
            int col = bn + nbase + ns * 8 + 2 * tg;
            if (col < N) {
                float b0 = hasBias ? bias[col]     : 0.f;
                float b1 = hasBias ? bias[col + 1] : 0.f;
                int r0 = bm + mbase + ms * 16 + g;
                float2 v0 = {acc[ms][ns].x + b0, acc[ms][ns].y + b1};
                float2 v1 = {acc[ms][ns].z + b0, acc[ms][ns].w + b1};
                *(float2*)&C[(size_t)r0 * N + col]       = v0;
                *(float2*)&C[(size_t)(r0 + 8) * N + col] = v1;
            }
        }
    }
}

// ============ fully fused causal attention (K-tile register prefetch) ============
__global__ __launch_bounds__(128) void attn_fused(const float* __restrict__ Qp,
                                                  const float* __restrict__ Kp,
                                                  const float* __restrict__ Vp,
                                                  float* __restrict__ attn,
                                                  float* __restrict__ Oh) {
    extern __shared__ float sm[];
    float (*Qs)[68] = (float(*)[68])sm;                 // 64x68
    float (*Es)[68] = (float(*)[68])(sm + 4352);        // 64x68
    float (*Ks)[68] = (float(*)[68])(sm + 8704);        // 64x68
    float (*Vs)[72] = (float(*)[72])(sm + 13056);       // 64x72
    float* lpart = sm + 17664;                          // 128
    float* linv  = lpart + 128;                         // 64

    int qt = gridDim.x - 1 - blockIdx.x;
    int bh = blockIdx.y;
    int b = bh >> 4, h = bh & 15;
    int q0 = qt * 64;

    int t = threadIdx.x;
    int warp = t >> 5, lane = t & 31;
    int g = lane >> 2, tg = lane & 3;
    int mbase = (warp & 1) * 32, nbase = (warp >> 1) * 32;

    int frow[8], fs[8];
    #pragma unroll
    for (int i = 0; i < 8; i++) { int idx = t + i * 128; frow[i] = idx >> 4; fs[i] = idx & 15; }

    float4 kr[8];
    auto fetchK = [&](int k0) {
        #pragma unroll
        for (int i = 0; i < 8; i++)
            kr[i] = *(const float4*)&Kp[(size_t)(b * Sn + k0 + frow[i]) * Dn + h * HEADn + fs[i] * 4];
    };
    auto storeK = [&]() {
        #pragma unroll
        for (int i = 0; i < 8; i++) {
            int row = frow[i], s = fs[i];
            Ks[row][s*4+0] = tf32_rna(kr[i].x); Ks[row][s*4+1] = tf32_rna(kr[i].y);
            Ks[row][s*4+2] = tf32_rna(kr[i].z); Ks[row][s*4+3] = tf32_rna(kr[i].w);
        }
    };

    // load Q tile (rna-rounded) — resident for both loops
    #pragma unroll
    for (int i = 0; i < 8; i++) {
        float4 v = *(const float4*)&Qp[(size_t)(b * Sn + q0 + frow[i]) * Dn + h * HEADn + fs[i] * 4];
        Qs[frow[i]][fs[i]*4+0] = tf32_rna(v.x); Qs[frow[i]][fs[i]*4+1] = tf32_rna(v.y);
        Qs[frow[i]][fs[i]*4+2] = tf32_rna(v.z); Qs[frow[i]][fs[i]*4+3] = tf32_rna(v.w);
    }

    float4 accp[2][4];
    #pragma unroll
    for (int i = 0; i < 2; i++)
        #pragma unroll
        for (int j = 0; j < 4; j++) accp[i][j] = make_float4(0.f, 0.f, 0.f, 0.f);
    float lacc[4] = {0.f, 0.f, 0.f, 0.f};

    size_t abase = (size_t)bh * Sn * Sn;

    // ---------------- loop 1: l and PV ----------------
    fetchK(0);
    for (int kt = 0; kt <= qt; kt++) {
        int k0 = kt * 64;
        storeK();                 // safe: Ks readers passed last iteration's sync #2
        __syncthreads();          // (1) Ks ready

        float4 accq[2][4];
        #pragma unroll
        for (int i = 0; i < 2; i++)
            #pragma unroll
            for (int j = 0; j < 4; j++) accq[i][j] = make_float4(0.f, 0.f, 0.f, 0.f);

        #pragma unroll
        for (int ko = 0; ko < 64; ko += 8) {
            float a[2][4];
            #pragma unroll
            for (int ms = 0; ms < 2; ms++) {
                int r = mbase + ms * 16;
                a[ms][0] = Qs[r+g][ko+tg];    a[ms][1] = Qs[r+g+8][ko+tg];
                a[ms][2] = Qs[r+g][ko+tg+4];  a[ms][3] = Qs[r+g+8][ko+tg+4];
            }
            #pragma unroll
            for (int ns = 0; ns < 4; ns++) {
                int c = nbase + ns * 8;
                float bb[2];
                bb[0] = Ks[c+g][ko+tg];  bb[1] = Ks[c+g][ko+tg+4];
                #pragma unroll
                for (int ms = 0; ms < 2; ms++) mma_tf32(accq[ms][ns], a[ms], bb);
            }
        }

        // epilogue: e = exp(s/8), causal mask, stage into Es
        #pragma unroll
        for (int ms = 0; ms < 2; ms++) {
            int rlo = mbase + ms * 16 + g;
            int rhi = rlo + 8;
            #pragma unroll
            for (int ns = 0; ns < 4; ns++) {
                int c0 = nbase + ns * 8 + 2 * tg;
                float ex = __expf(accq[ms][ns].x * 0.125f);
                float ey = __expf(accq[ms][ns].y * 0.125f);
                float ez = __expf(accq[ms][ns].z * 0.125f);
                float ew = __expf(accq[ms][ns].w * 0.125f);
                if (k0 + c0     > q0 + rlo) ex = 0.f;
                if (k0 + c0 + 1 > q0 + rlo) ey = 0.f;
                if (k0 + c0     > q0 + rhi) ez = 0.f;
                if (k0 + c0 + 1 > q0 + rhi) ew = 0.f;
                lacc[ms*2+0] += ex + ey;
                lacc[ms*2+1] += ez + ew;
                Es[rlo][c0] = tf32_rna(ex); Es[rlo][c0+1] = tf32_rna(ey);
                Es[rhi][c0] = tf32_rna(ez); Es[rhi][c0+1] = tf32_rna(ew);
            }
        }

        // load V tile
        #pragma unroll
        for (int i = 0; i < 8; i++) {
            float4 v = *(const float4*)&Vp[(size_t)(b * Sn + k0 + frow[i]) * Dn + h * HEADn + fs[i] * 4];
            Vs[frow[i]][fs[i]*4+0] = tf32_rna(v.x); Vs[frow[i]][fs[i]*4+1] = tf32_rna(v.y);
            Vs[frow[i]][fs[i]*4+2] = tf32_rna(v.z); Vs[frow[i]][fs[i]*4+3] = tf32_rna(v.w);
        }
        if (kt < qt) fetchK(k0 + 64);   // prefetch next K, hidden behind PV

        __syncthreads();          // (2) Es, Vs ready; QK reads of Ks done

        // PV
        #pragma unroll
        for (int ko = 0; ko < 64; ko += 8) {
            float a[2][4];
            #pragma unroll
            for (int ms = 0; ms < 2; ms++) {
                int r = mbase + ms * 16;
                a[ms][0] = Es[r+g][ko+tg];    a[ms][1] = Es[r+g+8][ko+tg];
                a[ms][2] = Es[r+g][ko+tg+4];  a[ms][3] = Es[r+g+8][ko+tg+4];
            }
            #pragma unroll
            for (int ns = 0; ns < 4; ns++) {
                int c = nbase + ns * 8;
                float bb[2];
                bb[0] = Vs[ko+tg][c+g];  bb[1] = Vs[ko+tg+4][c+g];
                #pragma unroll
                for (int ms = 0; ms < 2; ms++) mma_tf32(accp[ms][ns], a[ms], bb);
            }
        }
    }

    // ---------------- row sums -> linv ----------------
    #pragma unroll
    for (int i = 0; i < 4; i++) {
        lacc[i] += __shfl_xor_sync(0xffffffffu, lacc[i], 1);
        lacc[i] += __shfl_xor_sync(0xffffffffu, lacc[i], 2);
    }
    if (tg == 0) {
        #pragma unroll
        for (int ms = 0; ms < 2; ms++) {
            lpart[warp * 32 + ms * 16 + g]     = lacc[ms*2+0];
            lpart[warp * 32 + ms * 16 + 8 + g] = lacc[ms*2+1];
        }
    }
    __syncthreads();
    if (t < 64) {
        float l = (t < 32) ? (lpart[t] + lpart[64 + t])
                           : (lpart[32 + (t - 32)] + lpart[96 + (t - 32)]);
        linv[t] = 1.f / l;
    }
    __syncthreads();

    // normalized O tile
    #pragma unroll
    for (int ms = 0; ms < 2; ms++) {
        int rlo = mbase + ms * 16 + g;
        int rhi = rlo + 8;
        float ilo = linv[rlo], ihi = linv[rhi];
        #pragma unroll
        for (int ns = 0; ns < 4; ns++) {
            int c0 = nbase + ns * 8 + 2 * tg;
            float2 lo = {accp[ms][ns].x * ilo, accp[ms][ns].y * ilo};
            float2 hi = {accp[ms][ns].z * ihi, accp[ms][ns].w * ihi};
            *(float2*)&Oh[(size_t)(b * Sn + q0 + rlo) * Dn + h * HEADn + c0] = lo;
            *(float2*)&Oh[(size_t)(b * Sn + q0 + rhi) * Dn + h * HEADn + c0] = hi;
        }
    }

    // ---------------- loop 2: recompute scores, write normalized attn ----------------
    fetchK(0);
    for (int kt = 0; kt <= qt; kt++) {
        int k0 = kt * 64;
        __syncthreads();          // prior QK reads of Ks complete
        storeK();
        __syncthreads();          // Ks ready
        if (kt < qt) fetchK(k0 + 64);   // overlaps QK + epilogue

        float4 accq[2][4];
        #pragma unroll
        for (int i = 0; i < 2; i++)
            #pragma unroll
            for (int j = 0; j < 4; j++) accq[i][j] = make_float4(0.f, 0.f, 0.f, 0.f);

        #pragma unroll
        for (int ko = 0; ko < 64; ko += 8) {
            float a[2][4];
            #pragma unroll
            for (int ms = 0; ms < 2; ms++) {
                int r = mbase + ms * 16;
                a[ms][0] = Qs[r+g][ko+tg];    a[ms][1] = Qs[r+g+8][ko+tg];
                a[ms][2] = Qs[r+g][ko+tg+4];  a[ms][3] = Qs[r+g+8][ko+tg+4];
            }
            #pragma unroll
            for (int ns = 0; ns < 4; ns++) {
                int c = nbase + ns * 8;
                float bb[2];
                bb[0] = Ks[c+g][ko+tg];  bb[1] = Ks[c+g][ko+tg+4];
                #pragma unroll
                for (int ms = 0; ms < 2; ms++) mma_tf32(accq[ms][ns], a[ms], bb);
            }
        }

        #pragma unroll
        for (int ms = 0; ms < 2; ms++) {
            int rlo = mbase + ms * 16 + g;
            int rhi = rlo + 8;
            float ilo = linv[rlo], ihi = linv[rhi];
            #pragma unroll
            for (int ns = 0; ns < 4; ns++) {
                int c0 = nbase + ns * 8 + 2 * tg;
                float ex = __expf(accq[ms][ns].x * 0.125f);
                float ey = __expf(accq[ms][ns].y * 0.125f);
                float ez = __expf(accq[ms][ns].z * 0.125f);
                float ew = __expf(accq[ms][ns].w * 0.125f);
                if (k0 + c0     > q0 + rlo) ex = 0.f;
                if (k0 + c0 + 1 > q0 + rlo) ey = 0.f;
                if (k0 + c0     > q0 + rhi) ez = 0.f;
                if (k0 + c0 + 1 > q0 + rhi) ew = 0.f;
                float2 lo = {ex * ilo, ey * ilo};
                float2 hi = {ez * ihi, ew * ihi};
                *(float2*)&attn[abase + (size_t)(q0 + rlo) * Sn + k0 + c0] = lo;
                *(float2*)&attn[abase + (size_t)(q0 + rhi) * Sn + k0 + c0] = hi;
            }
        }
    }

    // zero-fill fully masked tiles
    float4 z4 = make_float4(0.f, 0.f, 0.f, 0.f);
    for (int kt = qt + 1; kt < Sn / 64; kt++) {
        int k0 = kt * 64;
        #pragma unroll
        for (int i = 0; i < 8; i++)
            *(float4*)&attn[abase + (size_t)(q0 + frow[i]) * Sn + k0 + fs[i] * 4] = z4;
    }
}

// ---------------- launch ----------------
extern "C" void kernel_launch(void* const* d_in, const int* in_sizes, int n_in,
                              void* d_out, int out_size) {
    (void)in_sizes; (void)n_in; (void)out_size;

    const float* q  = (const float*)d_in[0];
    const float* k  = (const float*)d_in[1];
    const float* v  = (const float*)d_in[2];
    const float* Vq = (const float*)d_in[3];
    const float* Uq = (const float*)d_in[4];
    const float* bq = (const float*)d_in[5];
    const float* Vk = (const float*)d_in[6];
    const float* Uk = (const float*)d_in[7];
    const float* bk = (const float*)d_in[8];
    const float* Vv = (const float*)d_in[9];
    const float* Uv = (const float*)d_in[10];
    const float* bv = (const float*)d_in[11];
    const float* Vo = (const float*)d_in[12];
    const float* Uo = (const float*)d_in[13];
    const float* bo = (const float*)d_in[14];

    float* out  = (float*)d_out;
    float* attn = out + (size_t)Mn * Dn;

    void *p_tmp, *p_split, *p_q, *p_k, *p_v, *p_oh;
    cudaGetSymbolAddress(&p_tmp, g_tmp);
    cudaGetSymbolAddress(&p_split, g_split);
    cudaGetSymbolAddress(&p_q, g_qp);
    cudaGetSymbolAddress(&p_k, g_kp);
    cudaGetSymbolAddress(&p_v, g_vp);
    cudaGetSymbolAddress(&p_oh, g_oh);

    float* tmp0 = (float*)p_tmp;
    float* tmp1 = tmp0 + (size_t)Mn * RANKn;
    float* tmp2 = tmp1 + (size_t)Mn * RANKn;
    float* spl  = (float*)p_split;
    float* gq = (float*)p_q;
    float* gk = (float*)p_k;
    float* gv = (float*)p_v;
    float* goh = (float*)p_oh;

    const size_t PSTRIDE = (size_t)Mn * RANKn;
    const int ATTN_SMEM = (4352 * 3 + 4608 + 128 + 64) * 4;   // 71424 B
    cudaFuncSetAttribute(attn_fused, cudaFuncAttributeMaxDynamicSharedMemorySize, ATTN_SMEM);

    // 1) down-projection q,k,v: tmp = x @ V^T
    GemmBatch g1;
    g1.A[0] = q;  g1.A[1] = k;  g1.A[2] = v;
    g1.Bp[0] = Vq; g1.Bp[1] = Vk; g1.Bp[2] = Vv;
    g1.bias[0] = g1.bias[1] = g1.bias[2] = nullptr;
    g1.C[0] = tmp0; g1.C[1] = tmp1; g1.C[2] = tmp2;
    gemm1x<<<dim3((RANKn + 63) / 64, Mn / 64, 3), 128>>>(g1, Mn, RANKn, Dn, 0, 1, 0, 0, 0);

    // 2) up-projection: proj = tmp @ U^T + b
    GemmBatch g2;
    g2.A[0] = tmp0; g2.A[1] = tmp1; g2.A[2] = tmp2;
    g2.Bp[0] = Uq; g2.Bp[1] = Uk; g2.Bp[2] = Uv;
    g2.bias[0] = bq; g2.bias[1] = bk; g2.bias[2] = bv;
    g2.C[0] = gq; g2.C[1] = gk; g2.C[2] = gv;
    gemm1x<<<dim3(Dn / 64, Mn / 64, 3), 128>>>(g2, Mn, Dn, RANKn, 1, 1, 0, 0, 0);

    // 3) fully fused attention
    attn_fused<<<dim3(Sn / 64, BHn), 128, ATTN_SMEM>>>(gq, gk, gv, attn, goh);

    // 4a) output down-projection, split-K=4 (grid 256 -> 1024 blocks)
    GemmBatch g3;
    g3.A[0] = goh; g3.Bp[0] = Vo; g3.bias[0] = nullptr; g3.C[0] = spl;
    g3.A[1] = g3.A[2] = nullptr; g3.Bp[1] = g3.Bp[2] = nullptr;
    g3.bias[1] = g3.bias[2] = nullptr; g3.C[1] = g3.C[2] = nullptr;
    gemm1x<<<dim3((RANKn + 63) / 64, Mn / 64, 4), 128>>>(g3, Mn, RANKn, Dn, 0, 4, PSTRIDE, 0, 0);

    // 4b) output up-projection, sums the 4 partials on A-load
    GemmBatch g4;
    g4.A[0] = spl; g4.Bp[0] = Uo; g4.bias[0] = bo; g4.C[0] = out;
    g4.A[1] = g4.A[2] = nullptr; g4.Bp[1] = g4.Bp[2] = nullptr;
    g4.bias[1] = g4.bias[2] = nullptr; g4.C[1] = g4.C[2] = nullptr;
    gemm1x<<<dim3(Dn / 64, Mn / 64, 1), 128>>>(g4, Mn, Dn, RANKn, 1, 1, 0, 4, PSTRIDE);
}